// round 9
// baseline (speedup 1.0000x reference)
#include <cuda_runtime.h>

// Problem constants
#define BATCH    32
#define CH       2048
#define SZ       4096
#define CSPLIT   16                 // c-dimension splits
#define CCHUNK   (CH / CSPLIT)      // 128 c iterations per block
#define BG       4                  // batches per block (w reuse factor)
#define TPB      128                // threads per block
#define S_PER_BLOCK (TPB * 4)       // 512 s-columns per block (float4/thread)
#define NSTREAM  (8 * 8 * CSPLIT)   // 1024 streaming blocks
#define NGROUPS  64                 // (8 s-tiles x 8 batch-groups)

// 8 MB partial-sum scratch + per-group arrival counters
__device__ float g_partial[CSPLIT * BATCH * SZ];
__device__ unsigned int g_count[NGROUPS];   // zero-init; reducer resets each run

// Streaming load (evict-first): 1 GiB of x must not thrash w out of L2
__device__ __forceinline__ float4 ldcs4(const float* p) {
    float4 v;
    asm volatile("ld.global.cs.v4.f32 {%0,%1,%2,%3}, [%4];"
                 : "=f"(v.x), "=f"(v.y), "=f"(v.z), "=f"(v.w) : "l"(p));
    return v;
}
// L2-scope load for partials (skip L1)
__device__ __forceinline__ float4 ldcg4(const float* p) {
    float4 v;
    asm volatile("ld.global.cg.v4.f32 {%0,%1,%2,%3}, [%4];"
                 : "=f"(v.x), "=f"(v.y), "=f"(v.z), "=f"(v.w) : "l"(p));
    return v;
}
__device__ __forceinline__ unsigned int ld_acquire(const unsigned int* p) {
    unsigned int v;
    asm volatile("ld.acquire.gpu.global.u32 %0, [%1];" : "=r"(v) : "l"(p));
    return v;
}

__global__ __launch_bounds__(TPB) void CWG_fused_kernel(
    const float* __restrict__ x,
    const float* __restrict__ w,
    const float* __restrict__ bias,
    float* __restrict__ out)
{
    const int bid = blockIdx.x;
    const int tid = threadIdx.x;

    if (bid < NSTREAM) {
        // ---------- streaming block: IDENTICAL body to the 158.5us R6 kernel ----------
        const int sx  = bid & 7;           // s-tile 0..7
        const int by  = (bid >> 3) & 7;    // batch-group 0..7
        const int cs  = bid >> 6;          // c-split 0..15
        const int s0  = sx * S_PER_BLOCK + tid * 4;
        const int b0  = by * BG;
        const int c0  = cs * CCHUNK;

        float4 acc[BG];
#pragma unroll
        for (int b = 0; b < BG; b++) acc[b] = make_float4(0.f, 0.f, 0.f, 0.f);

        const float* wp = w + (size_t)c0 * SZ + s0;
        const float* xp = x + ((size_t)b0 * CH + (size_t)c0) * SZ + s0;

#pragma unroll 4
        for (int c = 0; c < CCHUNK; c++) {
            const float4 wv = __ldg((const float4*)(wp + (size_t)c * SZ));
#pragma unroll
            for (int b = 0; b < BG; b++) {
                const float4 xv = ldcs4(xp + ((size_t)b * CH + (size_t)c) * SZ);
                acc[b].x = fmaf(xv.x, wv.x, acc[b].x);
                acc[b].y = fmaf(xv.y, wv.y, acc[b].y);
                acc[b].z = fmaf(xv.z, wv.z, acc[b].z);
                acc[b].w = fmaf(xv.w, wv.w, acc[b].w);
            }
        }

#pragma unroll
        for (int b = 0; b < BG; b++) {
            *(float4*)(g_partial + ((size_t)cs * BATCH + (size_t)(b0 + b)) * SZ + s0) = acc[b];
        }

        // release handshake (threadFenceReduction pattern; proven in R5's pass)
        __threadfence();
        __syncthreads();
        if (tid == 0)
            atomicAdd(&g_count[by * 8 + sx], 1u);
        return;
    }

    // ---------- dedicated reducer block (bids 1024..1087, scheduled last) ----------
    const int grp = bid - NSTREAM;          // 0..63
    const int sx  = grp & 7;
    const int by  = grp >> 3;
    const int b0  = by * BG;
    const int s0  = sx * S_PER_BLOCK + tid * 4;

    if (tid == 0) {
        while (ld_acquire(&g_count[grp]) != CSPLIT)
            __nanosleep(64);
        g_count[grp] = 0u;                  // reset for next graph replay
    }
    __syncthreads();
    __threadfence();                        // acquire side: order partial reads

    const float4 bv = *(const float4*)(bias + s0);
#pragma unroll
    for (int b = 0; b < BG; b++) {
        float4 sum = make_float4(0.f, 0.f, 0.f, 0.f);
        const float* base = g_partial + (size_t)(b0 + b) * SZ + s0;
#pragma unroll
        for (int k = 0; k < CSPLIT; k++) {  // fixed order => deterministic
            const float4 p = ldcg4(base + (size_t)k * BATCH * SZ);
            sum.x += p.x; sum.y += p.y; sum.z += p.z; sum.w += p.w;
        }
        float4 r;
        r.x = fmaxf(sum.x + bv.x, 0.f);
        r.y = fmaxf(sum.y + bv.y, 0.f);
        r.z = fmaxf(sum.z + bv.z, 0.f);
        r.w = fmaxf(sum.w + bv.w, 0.f);
        *(float4*)(out + (size_t)(b0 + b) * SZ + s0) = r;
    }
}

extern "C" void kernel_launch(void* const* d_in, const int* in_sizes, int n_in,
                              void* d_out, int out_size)
{
    const float* x    = (const float*)d_in[0];
    const float* w    = (const float*)d_in[1];
    const float* bias = (const float*)d_in[2];
    float* out        = (float*)d_out;

    CWG_fused_kernel<<<NSTREAM + NGROUPS, TPB>>>(x, w, bias, out);
}

// round 11
// speedup vs baseline: 1.0128x; 1.0128x over previous
#include <cuda_runtime.h>

// Problem constants
#define BATCH    32
#define CH       2048
#define SZ       4096

// Single fused kernel: 8 c-groups x 64 s-threads = 512 threads/block.
// All of c is covered inside the block -> outputs are FINAL (smem reduce),
// no global partials / second launch / cross-CTA sync.
// Grid 16x16 = 256 blocks x 512 thr = 131072 threads == R6's streaming
// thread count (R7's intra-block variant failed purely on thread count).
#define C_GROUPS   8
#define S_THREADS  64
#define TPB        (C_GROUPS * S_THREADS)     // 512
#define CCHUNK     (CH / C_GROUPS)            // 256 c-iterations per group
#define BG         2                          // batches per block
#define S_PER_BLOCK (S_THREADS * 4)           // 256 s-columns per block

// Streaming load (evict-first): 1 GiB of x must not thrash w out of L2
__device__ __forceinline__ float4 ldcs4(const float* p) {
    float4 v;
    asm volatile("ld.global.cs.v4.f32 {%0,%1,%2,%3}, [%4];"
                 : "=f"(v.x), "=f"(v.y), "=f"(v.z), "=f"(v.w) : "l"(p));
    return v;
}

__global__ __launch_bounds__(TPB) void CWG_fused_kernel(
    const float* __restrict__ x,
    const float* __restrict__ w,
    const float* __restrict__ bias,
    float* __restrict__ out)
{
    const int s_t = threadIdx.x & (S_THREADS - 1);   // 0..63
    const int cg  = threadIdx.x / S_THREADS;         // 0..7
    const int s0  = blockIdx.y * S_PER_BLOCK + s_t * 4;
    const int b0  = blockIdx.x * BG;                 // batch fastest-varying
    const int c0  = cg * CCHUNK;

    float4 acc[BG];
#pragma unroll
    for (int b = 0; b < BG; b++) acc[b] = make_float4(0.f, 0.f, 0.f, 0.f);

    const float* wp = w + (size_t)c0 * SZ + s0;
    const float* xp = x + ((size_t)b0 * CH + (size_t)c0) * SZ + s0;

#pragma unroll 4
    for (int c = 0; c < CCHUNK; c++) {
        const float4 wv = __ldg((const float4*)(wp + (size_t)c * SZ));
#pragma unroll
        for (int b = 0; b < BG; b++) {
            const float4 xv = ldcs4(xp + ((size_t)b * CH + (size_t)c) * SZ);
            acc[b].x = fmaf(xv.x, wv.x, acc[b].x);
            acc[b].y = fmaf(xv.y, wv.y, acc[b].y);
            acc[b].z = fmaf(xv.z, wv.z, acc[b].z);
            acc[b].w = fmaf(xv.w, wv.w, acc[b].w);
        }
    }

    // ---- intra-block c-group reduction via shared memory (16 KB) ----
    __shared__ float4 smem[C_GROUPS][S_THREADS][BG];
#pragma unroll
    for (int b = 0; b < BG; b++)
        smem[cg][s_t][b] = acc[b];
    __syncthreads();

    // 128 worker threads: one (s-position, batch) float4 output each.
    const int wk = threadIdx.x;
    if (wk < S_THREADS * BG) {
        const int b  = wk / S_THREADS;             // 0..1
        const int st = wk & (S_THREADS - 1);       // 0..63
        float4 sum = make_float4(0.f, 0.f, 0.f, 0.f);
#pragma unroll
        for (int g = 0; g < C_GROUPS; g++) {       // fixed order => deterministic
            const float4 p = smem[g][st][b];
            sum.x += p.x; sum.y += p.y; sum.z += p.z; sum.w += p.w;
        }
        const int sc = blockIdx.y * S_PER_BLOCK + st * 4;
        const float4 bv = *(const float4*)(bias + sc);
        float4 r;
        r.x = fmaxf(sum.x + bv.x, 0.f);
        r.y = fmaxf(sum.y + bv.y, 0.f);
        r.z = fmaxf(sum.z + bv.z, 0.f);
        r.w = fmaxf(sum.w + bv.w, 0.f);
        *(float4*)(out + (size_t)(b0 + b) * SZ + sc) = r;
    }
}

extern "C" void kernel_launch(void* const* d_in, const int* in_sizes, int n_in,
                              void* d_out, int out_size)
{
    const float* x    = (const float*)d_in[0];
    const float* w    = (const float*)d_in[1];
    const float* bias = (const float*)d_in[2];
    float* out        = (float*)d_out;

    // 16 batch-groups (fastest) x 16 s-tiles = 256 blocks, all co-resident.
    dim3 grid(BATCH / BG, SZ / S_PER_BLOCK);
    CWG_fused_kernel<<<grid, TPB>>>(x, w, bias, out);
}

// round 13
// speedup vs baseline: 1.0290x; 1.0160x over previous
#include <cuda_runtime.h>

// Problem constants
#define BATCH    32
#define CH       2048
#define SZ       4096
#define CSPLIT   16                 // c-dimension splits
#define CCHUNK   (CH / CSPLIT)      // 128 c iterations per block
#define BG       4                  // batches per block (w reuse factor)
#define TPB      128                // threads per block
#define S_PER_BLOCK (TPB * 4)       // 512 s-columns per block (float4/thread)

// 16 * 32 * 4096 floats = 8 MB partial-sum scratch
__device__ float g_partial[CSPLIT * BATCH * SZ];

// Streaming load (evict-first): 1 GiB of x must not thrash w out of L2
__device__ __forceinline__ float4 ldcs4(const float* p) {
    float4 v;
    asm volatile("ld.global.cs.v4.f32 {%0,%1,%2,%3}, [%4];"
                 : "=f"(v.x), "=f"(v.y), "=f"(v.z), "=f"(v.w) : "l"(p));
    return v;
}
// L2-scope load: partials may be L2-hot in replay; skip L1
__device__ __forceinline__ float4 ldcg4(const float* p) {
    float4 v;
    asm volatile("ld.global.cg.v4.f32 {%0,%1,%2,%3}, [%4];"
                 : "=f"(v.x), "=f"(v.y), "=f"(v.z), "=f"(v.w) : "l"(p));
    return v;
}

// ===== streaming stage: byte-identical to the 158.5us R6 kernel =====
__global__ __launch_bounds__(TPB) void CWG_partial_kernel(
    const float* __restrict__ x,
    const float* __restrict__ w)
{
    const int s0  = blockIdx.x * S_PER_BLOCK + threadIdx.x * 4;
    const int b0  = blockIdx.y * BG;
    const int cs  = blockIdx.z;
    const int c0  = cs * CCHUNK;

    float4 acc[BG];
#pragma unroll
    for (int b = 0; b < BG; b++) acc[b] = make_float4(0.f, 0.f, 0.f, 0.f);

    const float* wp = w + (size_t)c0 * SZ + s0;
    const float* xp = x + ((size_t)b0 * CH + (size_t)c0) * SZ + s0;

#pragma unroll 4
    for (int c = 0; c < CCHUNK; c++) {
        const float4 wv = __ldg((const float4*)(wp + (size_t)c * SZ));
#pragma unroll
        for (int b = 0; b < BG; b++) {
            const float4 xv = ldcs4(xp + ((size_t)b * CH + (size_t)c) * SZ);
            acc[b].x = fmaf(xv.x, wv.x, acc[b].x);
            acc[b].y = fmaf(xv.y, wv.y, acc[b].y);
            acc[b].z = fmaf(xv.z, wv.z, acc[b].z);
            acc[b].w = fmaf(xv.w, wv.w, acc[b].w);
        }
    }

#pragma unroll
    for (int b = 0; b < BG; b++) {
        *(float4*)(g_partial + ((size_t)cs * BATCH + (size_t)(b0 + b)) * SZ + s0) = acc[b];
    }
}

// ===== finalize: R6 body + PDL early-start =====
__global__ __launch_bounds__(128) void CWG_finalize_kernel(
    const float* __restrict__ bias,
    float* __restrict__ out)
{
    // Prologue runs EARLY (overlapped with the primary's tail under PDL):
    // index math + bias load (bias is a kernel input, independent of primary).
    const int i4 = blockIdx.x * 128 + threadIdx.x;   // float4 index
    const int i  = i4 * 4;                           // over BATCH*SZ = 131072
    const int s  = i & (SZ - 1);
    const float4 bv = __ldg((const float4*)(bias + s));

    // Gate only the partial reads on the primary kernel's completion.
    cudaGridDependencySynchronize();

    float4 sum = make_float4(0.f, 0.f, 0.f, 0.f);
#pragma unroll
    for (int k = 0; k < CSPLIT; k++) {
        const float4 p = ldcg4(g_partial + (size_t)k * BATCH * SZ + i);
        sum.x += p.x; sum.y += p.y; sum.z += p.z; sum.w += p.w;
    }

    float4 r;
    r.x = fmaxf(sum.x + bv.x, 0.f);
    r.y = fmaxf(sum.y + bv.y, 0.f);
    r.z = fmaxf(sum.z + bv.z, 0.f);
    r.w = fmaxf(sum.w + bv.w, 0.f);
    *(float4*)(out + i) = r;
}

extern "C" void kernel_launch(void* const* d_in, const int* in_sizes, int n_in,
                              void* d_out, int out_size)
{
    const float* x    = (const float*)d_in[0];
    const float* w    = (const float*)d_in[1];
    const float* bias = (const float*)d_in[2];
    float* out        = (float*)d_out;

    dim3 grid(SZ / S_PER_BLOCK, BATCH / BG, CSPLIT);  // (8, 8, 16) = 1024 blocks
    CWG_partial_kernel<<<grid, TPB>>>(x, w);

    // Secondary with programmatic stream serialization: its blocks may start
    // on SMs freed by the primary's retiring tail; gridDepSync above provides
    // the data dependency.
    cudaLaunchConfig_t cfg = {};
    cfg.gridDim  = dim3((BATCH * SZ / 4) / 128, 1, 1);   // 256 blocks
    cfg.blockDim = dim3(128, 1, 1);
    cfg.dynamicSmemBytes = 0;
    cfg.stream = 0;   // legacy default stream (same one <<<>>> used, capture-safe)
    cudaLaunchAttribute attr[1];
    attr[0].id = cudaLaunchAttributeProgrammaticStreamSerialization;
    attr[0].val.programmaticStreamSerializationAllowed = 1;
    cfg.attrs = attr;
    cfg.numAttrs = 1;
    cudaLaunchKernelEx(&cfg, CWG_finalize_kernel, bias, out);
}

// round 14
// speedup vs baseline: 1.0398x; 1.0105x over previous
#include <cuda_runtime.h>

// Problem constants
#define BATCH    32
#define CH       2048
#define SZ       4096

// Intra-block fusion with R6's EXACT per-thread streaming shape:
//   16 c-groups x 16 s-threads = 256 threads/block
//   per thread: BG=4 batches, 4 consecutive s (float4), CCHUNK=128 c-iters
// Grid = (8 batch-groups, 64 s-tiles) = 512 blocks x 256 = 131072 threads
// (same thread count / same inner loop as the 157.7us R13 streaming stage).
// The 16 c-splits reduce through 16KB of smem -> outputs are FINAL:
// no 8MB partial scratch, no 8.4MB DRAM re-read, no second launch.
#define C_GROUPS   16
#define S_THREADS  16
#define TPB        (C_GROUPS * S_THREADS)     // 256
#define CCHUNK     (CH / C_GROUPS)            // 128 c-iterations per group
#define BG         4                          // batches per block (w L2 reuse)
#define S_PER_BLOCK (S_THREADS * 4)           // 64 s-columns per block

// Streaming load (evict-first): 1 GiB of x must not thrash w out of L2
__device__ __forceinline__ float4 ldcs4(const float* p) {
    float4 v;
    asm volatile("ld.global.cs.v4.f32 {%0,%1,%2,%3}, [%4];"
                 : "=f"(v.x), "=f"(v.y), "=f"(v.z), "=f"(v.w) : "l"(p));
    return v;
}

__global__ __launch_bounds__(TPB) void CWG_fused_kernel(
    const float* __restrict__ x,
    const float* __restrict__ w,
    const float* __restrict__ bias,
    float* __restrict__ out)
{
    const int s_t = threadIdx.x & (S_THREADS - 1);   // 0..15
    const int cg  = threadIdx.x >> 4;                // 0..15 (c-split)
    const int s0  = blockIdx.y * S_PER_BLOCK + s_t * 4;
    const int b0  = blockIdx.x * BG;                 // batch fastest-varying:
    const int c0  = cg * CCHUNK;                     // same-w blocks co-scheduled

    float4 acc[BG];
#pragma unroll
    for (int b = 0; b < BG; b++) acc[b] = make_float4(0.f, 0.f, 0.f, 0.f);

    const float* wp = w + (size_t)c0 * SZ + s0;
    const float* xp = x + ((size_t)b0 * CH + (size_t)c0) * SZ + s0;

    // ---- byte-identical per-thread loop to the R6/R13 streaming kernel ----
#pragma unroll 4
    for (int c = 0; c < CCHUNK; c++) {
        const float4 wv = __ldg((const float4*)(wp + (size_t)c * SZ));
#pragma unroll
        for (int b = 0; b < BG; b++) {
            const float4 xv = ldcs4(xp + ((size_t)b * CH + (size_t)c) * SZ);
            acc[b].x = fmaf(xv.x, wv.x, acc[b].x);
            acc[b].y = fmaf(xv.y, wv.y, acc[b].y);
            acc[b].z = fmaf(xv.z, wv.z, acc[b].z);
            acc[b].w = fmaf(xv.w, wv.w, acc[b].w);
        }
    }

    // ---- 16-way c-group reduction via shared memory (16 KB) ----
    __shared__ float4 smem[C_GROUPS][S_THREADS][BG];
#pragma unroll
    for (int b = 0; b < BG; b++)
        smem[cg][s_t][b] = acc[b];
    __syncthreads();

    // 64 worker threads: one (s-position, batch) float4 output each.
    const int wk = threadIdx.x;
    if (wk < S_THREADS * BG) {
        const int b  = wk >> 4;                    // 0..3
        const int st = wk & (S_THREADS - 1);       // 0..15
        float4 sum = make_float4(0.f, 0.f, 0.f, 0.f);
#pragma unroll
        for (int g = 0; g < C_GROUPS; g++) {       // ascending g == R6's k-order
            const float4 p = smem[g][st][b];
            sum.x += p.x; sum.y += p.y; sum.z += p.z; sum.w += p.w;
        }
        const int sc = blockIdx.y * S_PER_BLOCK + st * 4;
        const float4 bv = *(const float4*)(bias + sc);
        float4 r;
        r.x = fmaxf(sum.x + bv.x, 0.f);
        r.y = fmaxf(sum.y + bv.y, 0.f);
        r.z = fmaxf(sum.z + bv.z, 0.f);
        r.w = fmaxf(sum.w + bv.w, 0.f);
        *(float4*)(out + (size_t)(b0 + b) * SZ + sc) = r;
    }
}

extern "C" void kernel_launch(void* const* d_in, const int* in_sizes, int n_in,
                              void* d_out, int out_size)
{
    const float* x    = (const float*)d_in[0];
    const float* w    = (const float*)d_in[1];
    const float* bias = (const float*)d_in[2];
    float* out        = (float*)d_out;

    // 8 batch-groups (fastest) x 64 s-tiles = 512 blocks, 4/SM co-resident.
    dim3 grid(BATCH / BG, SZ / S_PER_BLOCK);
    CWG_fused_kernel<<<grid, TPB>>>(x, w, bias, out);
}